// round 6
// baseline (speedup 1.0000x reference)
#include <cuda_runtime.h>
#include <cuda_bf16.h>

static constexpr int BS = 32;
static constexpr int S  = 2048;
static constexpr int H  = 1024;

// Scratch for v[b,h] = sum_k hidden[b,k] * W[k,h]  (device global: no allocs allowed)
__device__ float g_v[BS * H];

// ---------------------------------------------------------------------------
// Stage 0: zero the accumulator (graph replays: must not rely on load-time zero)
// ---------------------------------------------------------------------------
__global__ void zero_v_kernel() {
    g_v[blockIdx.x * blockDim.x + threadIdx.x] = 0.0f;
}

// ---------------------------------------------------------------------------
// Stage 1: v[b,h] = sum_k hidden[b,k] * W[k,h]
// grid: (H/128, BS/8, K/64) = (8, 4, 16) = 512 blocks, 128 threads.
// Each thread owns one h column, 8 batches, 64 k values; ~16 independent W
// loads in flight per warp; k-chunks reduce via atomicAdd (spread addrs).
// ---------------------------------------------------------------------------
__global__ void __launch_bounds__(128) v_kernel(const float* __restrict__ hidden,
                                                const float* __restrict__ W) {
    __shared__ float sh[8][64];
    const int h  = blockIdx.x * 128 + threadIdx.x;
    const int b0 = blockIdx.y * 8;
    const int k0 = blockIdx.z * 64;

#pragma unroll
    for (int i = threadIdx.x; i < 8 * 64; i += 128) {
        int bb = i >> 6, kk = i & 63;
        sh[bb][kk] = hidden[(b0 + bb) * H + (k0 + kk)];
    }
    __syncthreads();

    float acc[8];
#pragma unroll
    for (int bb = 0; bb < 8; bb++) acc[bb] = 0.0f;

#pragma unroll 16
    for (int kk = 0; kk < 64; kk++) {
        float w = W[(size_t)(k0 + kk) * H + h];   // coalesced across threads (h)
#pragma unroll
        for (int bb = 0; bb < 8; bb++)
            acc[bb] = fmaf(sh[bb][kk], w, acc[bb]);  // smem broadcast
    }

#pragma unroll
    for (int bb = 0; bb < 8; bb++)
        atomicAdd(&g_v[(b0 + bb) * H + h], acc[bb]);
}

// ---------------------------------------------------------------------------
// Stage 2: scores[b,s] = dot(enc[b,s,:], v[b,:])   -- the HBM-bound stage.
// One warp per (b,s). 1024-thread blocks = 32 warps covering 32 consecutive s
// of the SAME b, so the 4 KB v[b] tile is staged from L2 once per 32 rows
// (8 MB total LTS overhead vs 32 MB with 256-thread blocks — LTS is the
// binding resource, path-independent with the DRAM stream).
// enc read with __ldcs (268 MB single-use: evict-streaming, keep L2 clean).
// 8 independent LDG.128 in flight per lane.
// ---------------------------------------------------------------------------
__global__ void __launch_bounds__(1024) scores_kernel(const float* __restrict__ enc,
                                                      float* __restrict__ out) {
    __shared__ float4 shv[H / 4];  // 4 KB: v[b]
    const int warp = threadIdx.x >> 5;
    const int lane = threadIdx.x & 31;
    const int b = blockIdx.x >> 6;                   // 64 blocks per batch
    const int s = ((blockIdx.x & 63) << 5) + warp;   // 32 rows per block

    if (threadIdx.x < H / 4)
        shv[threadIdx.x] = ((const float4*)(g_v + b * H))[threadIdx.x];
    __syncthreads();

    const float4* e = (const float4*)(enc + ((size_t)b * S + s) * H);

    float a0 = 0.f, a1 = 0.f;
#pragma unroll
    for (int i = 0; i < 8; i++) {
        float4 x = __ldcs(e + lane + 32 * i);
        float4 v = shv[lane + 32 * i];
        a0 = fmaf(x.x, v.x, a0);
        a1 = fmaf(x.y, v.y, a1);
        a0 = fmaf(x.z, v.z, a0);
        a1 = fmaf(x.w, v.w, a1);
    }
    float acc = a0 + a1;
#pragma unroll
    for (int off = 16; off; off >>= 1)
        acc += __shfl_xor_sync(0xffffffffu, acc, off);
    if (lane == 0) out[b * S + s] = acc;
}

// ---------------------------------------------------------------------------
// Stage 3: in-place row softmax over S=2048. One 1024-thread block per batch
// row, 2 elements per thread (short dependency chains, high warp count).
// (Bias term c[b] is constant over s -> cancels in softmax; never computed.)
// ---------------------------------------------------------------------------
__global__ void __launch_bounds__(1024) softmax_kernel(float* __restrict__ out) {
    const int b    = blockIdx.x;
    const int tid  = threadIdx.x;
    const int warp = tid >> 5, lane = tid & 31;
    float* row = out + b * S;
    __shared__ float red[32];

    float v0 = row[tid];
    float v1 = row[tid + 1024];
    float m = fmaxf(v0, v1);
#pragma unroll
    for (int off = 16; off; off >>= 1)
        m = fmaxf(m, __shfl_xor_sync(0xffffffffu, m, off));
    if (lane == 0) red[warp] = m;
    __syncthreads();
    if (warp == 0) {
        float t = red[lane];
#pragma unroll
        for (int off = 16; off; off >>= 1)
            t = fmaxf(t, __shfl_xor_sync(0xffffffffu, t, off));
        red[lane] = t;
    }
    __syncthreads();
    const float M = red[0];

    v0 = __expf(v0 - M);
    v1 = __expf(v1 - M);
    float sum = v0 + v1;
#pragma unroll
    for (int off = 16; off; off >>= 1)
        sum += __shfl_xor_sync(0xffffffffu, sum, off);
    __syncthreads();               // red[] reuse hazard
    if (lane == 0) red[warp] = sum;
    __syncthreads();
    if (warp == 0) {
        float t = red[lane];
#pragma unroll
        for (int off = 16; off; off >>= 1)
            t += __shfl_xor_sync(0xffffffffu, t, off);
        red[lane] = t;
    }
    __syncthreads();
    const float inv = 1.0f / red[0];

    row[tid]        = v0 * inv;
    row[tid + 1024] = v1 * inv;
}

// ---------------------------------------------------------------------------
extern "C" void kernel_launch(void* const* d_in, const int* in_sizes, int n_in,
                              void* d_out, int out_size) {
    // Identify inputs by element count (all four sizes are distinct).
    const float* hidden = nullptr;  // 32768
    const float* enc    = nullptr;  // 67108864
    const float* W      = nullptr;  // 1048576
    for (int i = 0; i < n_in; i++) {
        long sz = in_sizes[i];
        if      (sz == (long)BS * S * H) enc    = (const float*)d_in[i];
        else if (sz == (long)H * H)      W      = (const float*)d_in[i];
        else if (sz == (long)BS * H)     hidden = (const float*)d_in[i];
        // bias (H) intentionally unused: softmax-invariant per-row constant
    }
    float* out = (float*)d_out;  // [BS, S] fp32

    zero_v_kernel<<<(BS * H) / 256, 256>>>();
    v_kernel<<<dim3(H / 128, BS / 8, 16), 128>>>(hidden, W);
    scores_kernel<<<(BS * S) / 32, 1024>>>(enc, out);
    softmax_kernel<<<BS, 1024>>>(out);
}

// round 7
// speedup vs baseline: 1.0038x; 1.0038x over previous
#include <cuda_runtime.h>
#include <cuda_bf16.h>

static constexpr int BS = 32;
static constexpr int S  = 2048;
static constexpr int H  = 1024;

// Device scratch (no allocs allowed in kernel_launch).
__device__ float  g_v[BS * H];          // v[b,h] = hidden[b] @ W
__device__ float2 g_part[BS * 256];     // per-(b, scores-block) online-softmax partial (max, sumexp)

// ---------------------------------------------------------------------------
// Stage 0: zero the v accumulator (graph replays: can't rely on load-time zero)
// ---------------------------------------------------------------------------
__global__ void zero_v_kernel() {
    g_v[blockIdx.x * blockDim.x + threadIdx.x] = 0.0f;
}

// ---------------------------------------------------------------------------
// Stage 1: v[b,h] = sum_k hidden[b,k] * W[k,h]
// grid: (H/128, BS/8, K/64) = (8, 4, 16) = 512 blocks, 128 threads.
// Each thread owns one h column, 8 batches, 64 k values; ~16 independent W
// loads in flight per warp; k-chunks reduce via atomicAdd (spread addrs).
// ---------------------------------------------------------------------------
__global__ void __launch_bounds__(128) v_kernel(const float* __restrict__ hidden,
                                                const float* __restrict__ W) {
    __shared__ float sh[8][64];
    const int h  = blockIdx.x * 128 + threadIdx.x;
    const int b0 = blockIdx.y * 8;
    const int k0 = blockIdx.z * 64;

#pragma unroll
    for (int i = threadIdx.x; i < 8 * 64; i += 128) {
        int bb = i >> 6, kk = i & 63;
        sh[bb][kk] = hidden[(b0 + bb) * H + (k0 + kk)];
    }
    __syncthreads();

    float acc[8];
#pragma unroll
    for (int bb = 0; bb < 8; bb++) acc[bb] = 0.0f;

#pragma unroll 16
    for (int kk = 0; kk < 64; kk++) {
        float w = W[(size_t)(k0 + kk) * H + h];   // coalesced across threads (h)
#pragma unroll
        for (int bb = 0; bb < 8; bb++)
            acc[bb] = fmaf(sh[bb][kk], w, acc[bb]);  // smem broadcast
    }

#pragma unroll
    for (int bb = 0; bb < 8; bb++)
        atomicAdd(&g_v[(b0 + bb) * H + h], acc[bb]);
}

// ---------------------------------------------------------------------------
// Stage 2: scores[b,s] = dot(enc[b,s,:], v[b,:])   -- the HBM-bound stage.
// Round-4 proven shape: 256-thread blocks, one warp per (b,s), 8 rows/block,
// v[b] staged in 4 KB smem, enc via __ldcs (268 MB single-use, streaming),
// 8 LDG.128 in flight per lane.
// NEW: each block also emits an online-softmax partial (max, sum of exp)
// over its 8 scores into g_part — removes the 2048-wide reduction chains
// from the final kernel.
// ---------------------------------------------------------------------------
__global__ void __launch_bounds__(256) scores_kernel(const float* __restrict__ enc,
                                                     float* __restrict__ out) {
    __shared__ float4 shv[H / 4];  // 4 KB: v[b]
    __shared__ float  s_sc[8];     // the block's 8 row scores
    const int warp = threadIdx.x >> 5;
    const int lane = threadIdx.x & 31;
    const int b     = blockIdx.x >> 8;               // 256 blocks per batch
    const int blkIB = blockIdx.x & 255;
    const int s     = (blkIB << 3) + warp;           // 8 rows per block

    const float4* vg = (const float4*)(g_v + b * H);
    for (int i = threadIdx.x; i < H / 4; i += 256) shv[i] = vg[i];
    __syncthreads();

    const float4* e = (const float4*)(enc + ((size_t)b * S + s) * H);

    float a0 = 0.f, a1 = 0.f;
#pragma unroll
    for (int i = 0; i < 8; i++) {
        float4 x = __ldcs(e + lane + 32 * i);
        float4 v = shv[lane + 32 * i];
        a0 = fmaf(x.x, v.x, a0);
        a1 = fmaf(x.y, v.y, a1);
        a0 = fmaf(x.z, v.z, a0);
        a1 = fmaf(x.w, v.w, a1);
    }
    float acc = a0 + a1;
#pragma unroll
    for (int off = 16; off; off >>= 1)
        acc += __shfl_xor_sync(0xffffffffu, acc, off);
    if (lane == 0) {
        out[b * S + s] = acc;
        s_sc[warp] = acc;
    }
    __syncthreads();

    // Warp 0: partial (max, sumexp) over this block's 8 scores.
    if (threadIdx.x < 32) {
        float v = (lane < 8) ? s_sc[lane] : -1e30f;
        float m = v;
#pragma unroll
        for (int off = 16; off; off >>= 1)
            m = fmaxf(m, __shfl_xor_sync(0xffffffffu, m, off));
        float ez = (lane < 8) ? __expf(v - m) : 0.f;
#pragma unroll
        for (int off = 16; off; off >>= 1)
            ez += __shfl_xor_sync(0xffffffffu, ez, off);
        if (lane == 0) g_part[b * 256 + blkIB] = make_float2(m, ez);
    }
}

// ---------------------------------------------------------------------------
// Stage 3: normalize. grid = BS*8 = 256 blocks, 256 threads. Block handles
// batch b = blk>>3, segment of 256 scores. Combines the 256 per-block partials
// (associative online-softmax merge) then writes exp(x - M) / Z.
// Launch-ramp overlapped across 256 CTAs; no long reduction chains.
// (Bias term c[b] is constant over s -> cancels in softmax; never computed.)
// ---------------------------------------------------------------------------
__global__ void __launch_bounds__(256) normalize_kernel(float* __restrict__ out) {
    const int b    = blockIdx.x >> 3;
    const int seg  = blockIdx.x & 7;
    const int tid  = threadIdx.x;
    const int warp = tid >> 5, lane = tid & 31;
    __shared__ float sm[8], sz[8];

    // Issue the score load early (independent of the partial combine).
    const int idx = b * S + seg * 256 + tid;
    const float x = out[idx];

    float2 p = g_part[b * 256 + tid];
    float m = p.x, z = p.y;
#pragma unroll
    for (int off = 16; off; off >>= 1) {
        float m2 = __shfl_xor_sync(0xffffffffu, m, off);
        float z2 = __shfl_xor_sync(0xffffffffu, z, off);
        float M  = fmaxf(m, m2);
        z = z * __expf(m - M) + z2 * __expf(m2 - M);
        m = M;
    }
    if (lane == 0) { sm[warp] = m; sz[warp] = z; }
    __syncthreads();
    if (warp == 0) {
        float m8 = (lane < 8) ? sm[lane] : -1e30f;
        float z8 = (lane < 8) ? sz[lane] : 0.f;
#pragma unroll
        for (int off = 4; off; off >>= 1) {
            float m2 = __shfl_xor_sync(0xffffffffu, m8, off);
            float z2 = __shfl_xor_sync(0xffffffffu, z8, off);
            float M  = fmaxf(m8, m2);
            z8 = z8 * __expf(m8 - M) + z2 * __expf(m2 - M);
            m8 = M;
        }
        if (lane == 0) { sm[0] = m8; sz[0] = z8; }
    }
    __syncthreads();

    const float M    = sm[0];
    const float invZ = 1.0f / sz[0];
    out[idx] = __expf(x - M) * invZ;
}

// ---------------------------------------------------------------------------
extern "C" void kernel_launch(void* const* d_in, const int* in_sizes, int n_in,
                              void* d_out, int out_size) {
    // Identify inputs by element count (all four sizes are distinct).
    const float* hidden = nullptr;  // 32768
    const float* enc    = nullptr;  // 67108864
    const float* W      = nullptr;  // 1048576
    for (int i = 0; i < n_in; i++) {
        long sz = in_sizes[i];
        if      (sz == (long)BS * S * H) enc    = (const float*)d_in[i];
        else if (sz == (long)H * H)      W      = (const float*)d_in[i];
        else if (sz == (long)BS * H)     hidden = (const float*)d_in[i];
        // bias (H) intentionally unused: softmax-invariant per-row constant
    }
    float* out = (float*)d_out;  // [BS, S] fp32

    zero_v_kernel<<<(BS * H) / 256, 256>>>();
    v_kernel<<<dim3(H / 128, BS / 8, 16), 128>>>(hidden, W);
    scores_kernel<<<(BS * S) / 8, 256>>>(enc, out);
    normalize_kernel<<<BS * 8, 256>>>(out);
}

// round 9
// speedup vs baseline: 1.0342x; 1.0303x over previous
#include <cuda_runtime.h>
#include <cuda_bf16.h>

static constexpr int BS = 32;
static constexpr int S  = 2048;
static constexpr int H  = 1024;

// Scratch for v[b,h] = hidden[b] @ W  (device global: no allocs allowed).
// Zeroed each launch via a captured cudaMemsetAsync node.
__device__ float g_v[BS * H];

// ---------------------------------------------------------------------------
// Stage 1: v[b,h] = sum_k hidden[b,k] * W[k,h]
// grid: (H/128, BS/8, K/64) = (8, 4, 16) = 512 blocks, 128 threads.
// Each thread owns one h column, 8 batches, 64 k values; ~16 independent W
// loads in flight per warp; k-chunks reduce via atomicAdd (spread addrs).
// Calls the PDL trigger early so the scores grid can pre-launch and park at
// its cudaGridDependencySynchronize().
// ---------------------------------------------------------------------------
__global__ void __launch_bounds__(128) v_kernel(const float* __restrict__ hidden,
                                                const float* __restrict__ W) {
    cudaTriggerProgrammaticLaunchCompletion();

    __shared__ float sh[8][64];
    const int h  = blockIdx.x * 128 + threadIdx.x;
    const int b0 = blockIdx.y * 8;
    const int k0 = blockIdx.z * 64;

#pragma unroll
    for (int i = threadIdx.x; i < 8 * 64; i += 128) {
        int bb = i >> 6, kk = i & 63;
        sh[bb][kk] = hidden[(b0 + bb) * H + (k0 + kk)];
    }
    __syncthreads();

    float acc[8];
#pragma unroll
    for (int bb = 0; bb < 8; bb++) acc[bb] = 0.0f;

#pragma unroll 16
    for (int kk = 0; kk < 64; kk++) {
        float w = W[(size_t)(k0 + kk) * H + h];   // coalesced across threads (h)
#pragma unroll
        for (int bb = 0; bb < 8; bb++)
            acc[bb] = fmaf(sh[bb][kk], w, acc[bb]);  // smem broadcast
    }

#pragma unroll
    for (int bb = 0; bb < 8; bb++)
        atomicAdd(&g_v[(b0 + bb) * H + h], acc[bb]);
}

// ---------------------------------------------------------------------------
// Stage 2: scores[b,s] = dot(enc[b,s,:], v[b,:])   -- the HBM-bound stage.
// Round-4 proven shape: 256-thread blocks, one warp per (b,s), 8 rows/block,
// v[b] staged in 4 KB smem, enc via __ldcs (268 MB single-use, streaming),
// 8 LDG.128 in flight per lane.
// PDL: launched with programmatic serialization against v_kernel; blocks may
// start during v_kernel's execution, so gridDependencySynchronize() before
// reading g_v. Triggers its own completion early so softmax pre-launches.
// ---------------------------------------------------------------------------
__global__ void __launch_bounds__(256) scores_kernel(const float* __restrict__ enc,
                                                     float* __restrict__ out) {
    __shared__ float4 shv[H / 4];  // 4 KB: v[b]
    const int warp = threadIdx.x >> 5;
    const int lane = threadIdx.x & 31;
    const int b = blockIdx.x >> 8;                  // 256 blocks per batch
    const int s = ((blockIdx.x & 255) << 3) + warp; // 8 rows per block

    cudaGridDependencySynchronize();                // wait: g_v complete
    cudaTriggerProgrammaticLaunchCompletion();      // allow softmax pre-launch

    const float4* vg = (const float4*)(g_v + b * H);
    for (int i = threadIdx.x; i < H / 4; i += 256) shv[i] = vg[i];
    __syncthreads();

    const float4* e = (const float4*)(enc + ((size_t)b * S + s) * H);

    float a0 = 0.f, a1 = 0.f;
#pragma unroll
    for (int i = 0; i < 8; i++) {
        float4 x = __ldcs(e + lane + 32 * i);
        float4 v = shv[lane + 32 * i];
        a0 = fmaf(x.x, v.x, a0);
        a1 = fmaf(x.y, v.y, a1);
        a0 = fmaf(x.z, v.z, a0);
        a1 = fmaf(x.w, v.w, a1);
    }
    float acc = a0 + a1;
#pragma unroll
    for (int off = 16; off; off >>= 1)
        acc += __shfl_xor_sync(0xffffffffu, acc, off);
    if (lane == 0) out[b * S + s] = acc;
}

// ---------------------------------------------------------------------------
// Stage 3: in-place row softmax over S=2048. One block per batch row
// (round-4 proven 32x256 shape). PDL: blocks pre-launch during scores' tail,
// park at gridDependencySynchronize, then run with zero launch-ramp cost.
// (Bias term c[b] is constant over s -> cancels in softmax; never computed.)
// ---------------------------------------------------------------------------
__global__ void __launch_bounds__(256) softmax_kernel(float* __restrict__ out) {
    const int b    = blockIdx.x;
    const int tid  = threadIdx.x;
    const int warp = tid >> 5, lane = tid & 31;
    float* row = out + b * S;
    __shared__ float red[8];

    cudaGridDependencySynchronize();                // wait: scores complete

    float v[8];
    float m = -1e30f;
#pragma unroll
    for (int i = 0; i < 8; i++) {
        v[i] = row[tid + 256 * i];
        m = fmaxf(m, v[i]);
    }
#pragma unroll
    for (int off = 16; off; off >>= 1)
        m = fmaxf(m, __shfl_xor_sync(0xffffffffu, m, off));
    if (lane == 0) red[warp] = m;
    __syncthreads();
    float M = red[0];
#pragma unroll
    for (int w = 1; w < 8; w++) M = fmaxf(M, red[w]);

    float sum = 0.f;
#pragma unroll
    for (int i = 0; i < 8; i++) {
        v[i] = __expf(v[i] - M);
        sum += v[i];
    }
#pragma unroll
    for (int off = 16; off; off >>= 1)
        sum += __shfl_xor_sync(0xffffffffu, sum, off);
    __syncthreads();               // red[] reuse hazard
    if (lane == 0) red[warp] = sum;
    __syncthreads();
    float T = 0.f;
#pragma unroll
    for (int w = 0; w < 8; w++) T += red[w];
    float inv = 1.0f / T;
#pragma unroll
    for (int i = 0; i < 8; i++)
        row[tid + 256 * i] = v[i] * inv;
}

// ---------------------------------------------------------------------------
extern "C" void kernel_launch(void* const* d_in, const int* in_sizes, int n_in,
                              void* d_out, int out_size) {
    // Identify inputs by element count (all four sizes are distinct).
    const float* hidden = nullptr;  // 32768
    const float* enc    = nullptr;  // 67108864
    const float* W      = nullptr;  // 1048576
    for (int i = 0; i < n_in; i++) {
        long sz = in_sizes[i];
        if      (sz == (long)BS * S * H) enc    = (const float*)d_in[i];
        else if (sz == (long)H * H)      W      = (const float*)d_in[i];
        else if (sz == (long)BS * H)     hidden = (const float*)d_in[i];
        // bias (H) intentionally unused: softmax-invariant per-row constant
    }
    float* out = (float*)d_out;  // [BS, S] fp32

    // Stage 0: zero g_v via a captured memset node (no kernel launch).
    void* vptr = nullptr;
    cudaGetSymbolAddress(&vptr, g_v);
    cudaMemsetAsync(vptr, 0, sizeof(float) * BS * H, 0);

    // Stage 1: plain launch (full dependency on the memset node).
    v_kernel<<<dim3(H / 128, BS / 8, 16), 128>>>(hidden, W);

    // Stages 2+3: PDL launches — overlap each kernel's launch/ramp with the
    // predecessor's execution; device-side gridDependencySynchronize provides
    // the data-ordering barrier.
    cudaLaunchAttribute attrs[1];
    attrs[0].id = cudaLaunchAttributeProgrammaticStreamSerialization;
    attrs[0].val.programmaticStreamSerializationAllowed = 1;

    {
        cudaLaunchConfig_t cfg = {};
        cfg.gridDim  = dim3((BS * S) / 8);
        cfg.blockDim = dim3(256);
        cfg.stream   = 0;
        cfg.attrs    = attrs;
        cfg.numAttrs = 1;
        cudaLaunchKernelEx(&cfg, scores_kernel, enc, out);
    }
    {
        cudaLaunchConfig_t cfg = {};
        cfg.gridDim  = dim3(BS);
        cfg.blockDim = dim3(256);
        cfg.stream   = 0;
        cfg.attrs    = attrs;
        cfg.numAttrs = 1;
        cudaLaunchKernelEx(&cfg, softmax_kernel, out);
    }
}